// round 2
// baseline (speedup 1.0000x reference)
#include <cuda_runtime.h>
#include <cuda_bf16.h>

#ifndef THR
#define THR 0.3f
#endif

// Each thread processes 8 rows:
//   loads  : 4 x float4 (16 floats = 8 rows of (h, junk)), front-batched -> MLP_p1 = 4
//   stores : 6 x float4 (24 floats = 8 rows x 3 outputs)
// All accesses use streaming (evict-first) hints: zero reuse in this kernel.
__global__ void __launch_bounds__(256) weighting_router_kernel8(
    const float4* __restrict__ xin,   // N/2 float4 (each float4 = 2 rows)
    float4* __restrict__ out,         // 3N/4 float4
    int n_oct)                        // N/8
{
    int q = blockIdx.x * blockDim.x + threadIdx.x;
    if (q >= n_oct) return;

    // rows [8q, 8q+7]: input float4 indices 4q .. 4q+3
    const float4* src = xin + 4 * (long long)q;
    float4 a = __ldcs(src + 0);
    float4 b = __ldcs(src + 1);
    float4 c = __ldcs(src + 2);
    float4 d = __ldcs(src + 3);

    const float inv_hi = 1.0f / (1.0f - THR);  // 1/0.7
    const float inv_lo = 1.0f / THR;           // 1/0.3

    float h[8] = {a.x, a.z, b.x, b.z, c.x, c.z, d.x, d.z};
    float o[24];

#pragma unroll
    for (int i = 0; i < 8; i++) {
        float hv = h[i];
        bool hi = (hv >= THR);
        o[3 * i + 0] = hi ? (hv - THR) * inv_hi : 0.0f;
        o[3 * i + 1] = hi ? 0.0f : (THR - hv) * inv_lo;
        o[3 * i + 2] = hi ? (1.0f - hv) * inv_hi : hv * inv_lo;
    }

    float4* dst = out + 6 * (long long)q;
#pragma unroll
    for (int j = 0; j < 6; j++) {
        __stcs(dst + j, make_float4(o[4 * j + 0], o[4 * j + 1],
                                    o[4 * j + 2], o[4 * j + 3]));
    }
}

// Tail handler for rows not covered by the vectorized kernel (n % 8 != 0).
__global__ void weighting_router_tail(
    const float* __restrict__ x,
    float* __restrict__ out,
    int start_row, int n_rows)
{
    int i = start_row + blockIdx.x * blockDim.x + threadIdx.x;
    if (i >= n_rows) return;

    const float inv_hi = 1.0f / (1.0f - THR);
    const float inv_lo = 1.0f / THR;

    float hv = x[2 * i];
    bool hi = (hv >= THR);
    out[3 * i + 0] = hi ? (hv - THR) * inv_hi : 0.0f;
    out[3 * i + 1] = hi ? 0.0f : (THR - hv) * inv_lo;
    out[3 * i + 2] = hi ? (1.0f - hv) * inv_hi : hv * inv_lo;
}

extern "C" void kernel_launch(void* const* d_in, const int* in_sizes, int n_in,
                              void* d_out, int out_size)
{
    const float* x = (const float*)d_in[0];
    float* out = (float*)d_out;

    int n_rows = in_sizes[0] / 2;     // x is (N, 2)
    int n_oct = n_rows / 8;

    if (n_oct > 0) {
        int threads = 256;
        int blocks = (n_oct + threads - 1) / threads;
        weighting_router_kernel8<<<blocks, threads>>>(
            (const float4*)x, (float4*)out, n_oct);
    }

    int done = n_oct * 8;
    int rem = n_rows - done;
    if (rem > 0) {
        int threads = 128;
        int blocks = (rem + threads - 1) / threads;
        weighting_router_tail<<<blocks, threads>>>(x, out, done, n_rows);
    }
}

// round 3
// speedup vs baseline: 1.2163x; 1.2163x over previous
#include <cuda_runtime.h>
#include <cuda_bf16.h>

#ifndef THR
#define THR 0.3f
#endif

// R1 structure (best so far): 4 rows/thread.
//   loads  : 2 x float4 via __ldcs (input has zero reuse -> evict-first,
//            keep L2 capacity for the write stream)
//   stores : 3 x float4, DEFAULT policy (.cs on stores regressed in R2)
__global__ void __launch_bounds__(256) weighting_router_kernel(
    const float4* __restrict__ xin,   // N/2 float4 (each float4 = 2 rows)
    float4* __restrict__ out,         // 3N/4 float4
    int n_quads)                      // N/4
{
    int q = blockIdx.x * blockDim.x + threadIdx.x;
    if (q >= n_quads) return;

    float4 a = __ldcs(xin + 2 * q);
    float4 b = __ldcs(xin + 2 * q + 1);

    const float inv_hi = 1.0f / (1.0f - THR);  // 1/0.7
    const float inv_lo = 1.0f / THR;           // 1/0.3

    float h[4] = {a.x, a.z, b.x, b.z};
    float o[12];

#pragma unroll
    for (int i = 0; i < 4; i++) {
        float hv = h[i];
        bool hi = (hv >= THR);
        o[3 * i + 0] = hi ? (hv - THR) * inv_hi : 0.0f;
        o[3 * i + 1] = hi ? 0.0f : (THR - hv) * inv_lo;
        o[3 * i + 2] = hi ? (1.0f - hv) * inv_hi : hv * inv_lo;
    }

    float4* dst = out + 3 * q;
    dst[0] = make_float4(o[0], o[1], o[2],  o[3]);
    dst[1] = make_float4(o[4], o[5], o[6],  o[7]);
    dst[2] = make_float4(o[8], o[9], o[10], o[11]);
}

// Tail handler for rows not covered by the vectorized kernel (n % 4 != 0).
__global__ void weighting_router_tail(
    const float* __restrict__ x,
    float* __restrict__ out,
    int start_row, int n_rows)
{
    int i = start_row + blockIdx.x * blockDim.x + threadIdx.x;
    if (i >= n_rows) return;

    const float inv_hi = 1.0f / (1.0f - THR);
    const float inv_lo = 1.0f / THR;

    float hv = x[2 * i];
    bool hi = (hv >= THR);
    out[3 * i + 0] = hi ? (hv - THR) * inv_hi : 0.0f;
    out[3 * i + 1] = hi ? 0.0f : (THR - hv) * inv_lo;
    out[3 * i + 2] = hi ? (1.0f - hv) * inv_hi : hv * inv_lo;
}

extern "C" void kernel_launch(void* const* d_in, const int* in_sizes, int n_in,
                              void* d_out, int out_size)
{
    const float* x = (const float*)d_in[0];
    float* out = (float*)d_out;

    int n_rows = in_sizes[0] / 2;     // x is (N, 2)
    int n_quads = n_rows / 4;

    if (n_quads > 0) {
        int threads = 256;
        int blocks = (n_quads + threads - 1) / threads;
        weighting_router_kernel<<<blocks, threads>>>(
            (const float4*)x, (float4*)out, n_quads);
    }

    int done = n_quads * 4;
    int rem = n_rows - done;
    if (rem > 0) {
        int threads = 128;
        int blocks = (rem + threads - 1) / threads;
        weighting_router_tail<<<blocks, threads>>>(x, out, done, n_rows);
    }
}

// round 4
// speedup vs baseline: 1.2524x; 1.0296x over previous
#include <cuda_runtime.h>
#include <cuda_bf16.h>

#ifndef THR
#define THR 0.3f
#endif

// 256 threads handle 1024 rows per block.
// All global loads/stores are warp-contiguous 128-bit accesses (4 lines per
// wavefront). Output is assembled in shared memory to decouple the row-major
// 3-float output layout from the coalesced store pattern.
__global__ void __launch_bounds__(256) weighting_router_smem(
    const float4* __restrict__ xin,   // N/2 float4 (each float4 = 2 rows)
    float4* __restrict__ out)         // 3N/4 float4
{
    __shared__ float s[3072];         // 1024 rows * 3 outputs = 12 KB

    const int tid = threadIdx.x;
    const long long blk = blockIdx.x;

    // ---- coalesced loads: warp spans 512B contiguous per LDG.128 ----
    const float4* src = xin + blk * 512;        // 512 float4 = 1024 rows
    float4 a = src[tid];                        // rows 2*tid,     2*tid + 1
    float4 b = src[tid + 256];                  // rows 2*tid+512, 2*tid + 513

    const float inv_hi = 1.0f / (1.0f - THR);   // 1/0.7
    const float inv_lo = 1.0f / THR;            // 1/0.3

    float h[4] = {a.x, a.z, b.x, b.z};
    float o[12];

#pragma unroll
    for (int i = 0; i < 4; i++) {
        float hv = h[i];
        bool hi = (hv >= THR);
        o[3 * i + 0] = hi ? (hv - THR) * inv_hi : 0.0f;
        o[3 * i + 1] = hi ? 0.0f : (THR - hv) * inv_lo;
        o[3 * i + 2] = hi ? (1.0f - hv) * inv_hi : hv * inv_lo;
    }

    // rows 2*tid, 2*tid+1      -> smem floats [6*tid       .. 6*tid+5]
    // rows 2*tid+512, 2*tid+513-> smem floats [6*tid+1536  .. 6*tid+1541]
    float2* s2 = (float2*)s;
#pragma unroll
    for (int j = 0; j < 3; j++)
        s2[3 * tid + j]       = make_float2(o[2 * j],     o[2 * j + 1]);
#pragma unroll
    for (int j = 0; j < 3; j++)
        s2[3 * tid + 768 + j] = make_float2(o[6 + 2 * j], o[6 + 2 * j + 1]);

    __syncthreads();

    // ---- coalesced stores: warp spans 512B contiguous per STG.128 ----
    const float4* s4 = (const float4*)s;        // 768 float4
    float4* dst = out + blk * 768;
    dst[tid]       = s4[tid];
    dst[tid + 256] = s4[tid + 256];
    dst[tid + 512] = s4[tid + 512];
}

// Tail handler for rows not covered by the block-tiled kernel (n % 1024 != 0).
__global__ void weighting_router_tail(
    const float* __restrict__ x,
    float* __restrict__ out,
    int start_row, int n_rows)
{
    int i = start_row + blockIdx.x * blockDim.x + threadIdx.x;
    if (i >= n_rows) return;

    const float inv_hi = 1.0f / (1.0f - THR);
    const float inv_lo = 1.0f / THR;

    float hv = x[2 * i];
    bool hi = (hv >= THR);
    out[3 * i + 0] = hi ? (hv - THR) * inv_hi : 0.0f;
    out[3 * i + 1] = hi ? 0.0f : (THR - hv) * inv_lo;
    out[3 * i + 2] = hi ? (1.0f - hv) * inv_hi : hv * inv_lo;
}

extern "C" void kernel_launch(void* const* d_in, const int* in_sizes, int n_in,
                              void* d_out, int out_size)
{
    const float* x = (const float*)d_in[0];
    float* out = (float*)d_out;

    int n_rows = in_sizes[0] / 2;     // x is (N, 2)
    int n_blocks = n_rows / 1024;

    if (n_blocks > 0) {
        weighting_router_smem<<<n_blocks, 256>>>(
            (const float4*)x, (float4*)out);
    }

    int done = n_blocks * 1024;
    int rem = n_rows - done;
    if (rem > 0) {
        int threads = 128;
        int blocks = (rem + threads - 1) / threads;
        weighting_router_tail<<<blocks, threads>>>(x, out, done, n_rows);
    }
}

// round 5
// speedup vs baseline: 1.2576x; 1.0042x over previous
#include <cuda_runtime.h>
#include <cuda_bf16.h>
#include <cstdint>

#ifndef THR
#define THR 0.3f
#endif

// 512 threads handle 2048 rows per block (24 KB output tile).
// Loads: warp-contiguous LDG.128. Output assembled in smem, then stored with a
// single 1D TMA bulk copy (cp.async.bulk) — no LDS readback, no STG wavefronts.
__global__ void __launch_bounds__(512) weighting_router_tma(
    const float4* __restrict__ xin,   // N/2 float4 (each float4 = 2 rows)
    float* __restrict__ out)          // 3N floats
{
    __shared__ __align__(128) float s[6144];   // 2048 rows * 3 = 24 KB

    const int tid = threadIdx.x;
    const long long blk = blockIdx.x;

    // ---- coalesced loads: warp spans 512B contiguous per LDG.128 ----
    const float4* src = xin + blk * 1024;       // 1024 float4 = 2048 rows
    float4 a = src[tid];                        // rows 2*tid,      2*tid+1
    float4 b = src[tid + 512];                  // rows 2*tid+1024, 2*tid+1025

    const float inv_hi = 1.0f / (1.0f - THR);   // 1/0.7
    const float inv_lo = 1.0f / THR;            // 1/0.3

    float h[4] = {a.x, a.z, b.x, b.z};
    float o[12];

#pragma unroll
    for (int i = 0; i < 4; i++) {
        float hv = h[i];
        bool hi = (hv >= THR);
        o[3 * i + 0] = hi ? (hv - THR) * inv_hi : 0.0f;
        o[3 * i + 1] = hi ? 0.0f : (THR - hv) * inv_lo;
        o[3 * i + 2] = hi ? (1.0f - hv) * inv_hi : hv * inv_lo;
    }

    // rows 2*tid,2*tid+1       -> floats [6*tid      .. 6*tid+5]    (f2 idx 3*tid)
    // rows 2*tid+1024,+1025    -> floats [6*tid+3072 .. 6*tid+3077] (f2 idx 3*tid+1536)
    float2* s2 = (float2*)s;
#pragma unroll
    for (int j = 0; j < 3; j++)
        s2[3 * tid + j]        = make_float2(o[2 * j],     o[2 * j + 1]);
#pragma unroll
    for (int j = 0; j < 3; j++)
        s2[3 * tid + 1536 + j] = make_float2(o[6 + 2 * j], o[6 + 2 * j + 1]);

    __syncthreads();

    // ---- single bulk TMA store: smem -> gmem, 24 KB ----
    if (tid == 0) {
        float* dst = out + blk * 6144;
        uint32_t smem_addr = (uint32_t)__cvta_generic_to_shared(s);
        // Make generic-proxy smem writes visible to the async proxy.
        asm volatile("fence.proxy.async.shared::cta;" ::: "memory");
        asm volatile(
            "cp.async.bulk.global.shared::cta.bulk_group [%0], [%1], %2;"
            :: "l"(dst), "r"(smem_addr), "r"(24576) : "memory");
        asm volatile("cp.async.bulk.commit_group;" ::: "memory");
        asm volatile("cp.async.bulk.wait_group 0;" ::: "memory");
    }
}

// Tail handler for rows not covered by the block-tiled kernel (n % 2048 != 0).
__global__ void weighting_router_tail(
    const float* __restrict__ x,
    float* __restrict__ out,
    int start_row, int n_rows)
{
    int i = start_row + blockIdx.x * blockDim.x + threadIdx.x;
    if (i >= n_rows) return;

    const float inv_hi = 1.0f / (1.0f - THR);
    const float inv_lo = 1.0f / THR;

    float hv = x[2 * i];
    bool hi = (hv >= THR);
    out[3 * i + 0] = hi ? (hv - THR) * inv_hi : 0.0f;
    out[3 * i + 1] = hi ? 0.0f : (THR - hv) * inv_lo;
    out[3 * i + 2] = hi ? (1.0f - hv) * inv_hi : hv * inv_lo;
}

extern "C" void kernel_launch(void* const* d_in, const int* in_sizes, int n_in,
                              void* d_out, int out_size)
{
    const float* x = (const float*)d_in[0];
    float* out = (float*)d_out;

    int n_rows = in_sizes[0] / 2;     // x is (N, 2)
    int n_blocks = n_rows / 2048;

    if (n_blocks > 0) {
        weighting_router_tma<<<n_blocks, 512>>>(
            (const float4*)x, out);
    }

    int done = n_blocks * 2048;
    int rem = n_rows - done;
    if (rem > 0) {
        int threads = 128;
        int blocks = (rem + threads - 1) / threads;
        weighting_router_tail<<<blocks, threads>>>(x, out, done, n_rows);
    }
}